// round 2
// baseline (speedup 1.0000x reference)
#include <cuda_runtime.h>
#include <math.h>

// Problem constants
#define B_   8
#define L_   1024
#define S_   1000
#define H_   8
#define E_   128
#define DM   1024
#define DL   4096
#define INNER_ 1024

// Scratch (allocation-free: __device__ globals)
__device__ float g_Q[B_ * L_ * INNER_];   // (B*L, H*E)
__device__ float g_K[S_ * INNER_];        // (S, H*E)
__device__ float g_V[S_ * INNER_];        // (S, H*E)
__device__ float g_A[B_ * L_ * INNER_];   // attention out (B*L, H*E)

// ---------------------------------------------------------------------------
// Tiled fp32 GEMM: C[M,N] = A[M,K] @ B[K,N] + bias[N]
// BM=64, BN=64, BK=16, 256 threads, 4x4 register tile per thread.
// N and K must be multiples of 64/16 (true for all 4 uses); M may be ragged.
// ---------------------------------------------------------------------------
__global__ __launch_bounds__(256)
void gemm_bias_kernel(const float* __restrict__ A,
                      const float* __restrict__ B,
                      const float* __restrict__ bias,
                      float* __restrict__ C,
                      int M, int N, int K) {
    __shared__ float As[16][68];   // transposed A tile, padded
    __shared__ float Bs[16][64];

    const int t  = threadIdx.x;
    const int bm = blockIdx.y * 64;
    const int bn = blockIdx.x * 64;

    const int tm = (t >> 4) * 4;       // 0..60
    const int tn = (t & 15) * 4;       // 0..60

    // loader indices
    const int arow = t >> 2;           // 0..63
    const int ak   = (t & 3) * 4;      // 0,4,8,12
    const int brow = t >> 4;           // 0..15
    const int bn4  = (t & 15) * 4;     // 0..60

    float acc[4][4] = {};

    for (int k0 = 0; k0 < K; k0 += 16) {
        float4 a4 = make_float4(0.f, 0.f, 0.f, 0.f);
        if (bm + arow < M)
            a4 = *(const float4*)(A + (size_t)(bm + arow) * K + k0 + ak);
        As[ak + 0][arow] = a4.x;
        As[ak + 1][arow] = a4.y;
        As[ak + 2][arow] = a4.z;
        As[ak + 3][arow] = a4.w;

        *(float4*)&Bs[brow][bn4] =
            *(const float4*)(B + (size_t)(k0 + brow) * N + bn + bn4);

        __syncthreads();

        #pragma unroll
        for (int kk = 0; kk < 16; kk++) {
            float4 av = *(float4*)&As[kk][tm];
            float4 bv = *(float4*)&Bs[kk][tn];
            float ar[4] = {av.x, av.y, av.z, av.w};
            float br[4] = {bv.x, bv.y, bv.z, bv.w};
            #pragma unroll
            for (int i = 0; i < 4; i++)
                #pragma unroll
                for (int j = 0; j < 4; j++)
                    acc[i][j] += ar[i] * br[j];
        }
        __syncthreads();
    }

    float4 b4 = *(const float4*)(bias + bn + tn);
    #pragma unroll
    for (int i = 0; i < 4; i++) {
        int row = bm + tm + i;
        if (row < M) {
            float4 o;
            o.x = acc[i][0] + b4.x;
            o.y = acc[i][1] + b4.y;
            o.z = acc[i][2] + b4.z;
            o.w = acc[i][3] + b4.w;
            *(float4*)(C + (size_t)row * N + bn + tn) = o;
        }
    }
}

// ---------------------------------------------------------------------------
// Fused attention: per (b, h, 16-row L tile), flash-style online softmax
// over S=1000 in chunks of 64. fp32 throughout.
// Q: (B*L, H*E), K/V: (S, H*E), O: (B*L, H*E)
// ---------------------------------------------------------------------------
#define TL 16
#define TS 64

// XOR swizzle on float4 columns of the KV tile: kills step-4-row conflicts
// in the score phase while keeping AV-phase reads conflict-free.
__device__ __forceinline__ float4* kvp(float (*kv)[128], int srow, int c4) {
    return (float4*)&kv[srow][((c4 ^ (srow >> 2)) & 31) << 2];
}

__global__ __launch_bounds__(256)
void attn_kernel(const float* __restrict__ Q,
                 const float* __restrict__ K,
                 const float* __restrict__ V,
                 float* __restrict__ O) {
    __shared__ float q_s[TL][128];
    __shared__ float kv_s[TS][128];
    __shared__ float sc_s[TL][TS];
    __shared__ float m_s[TL], l_s[TL], alpha_s[TL];

    const int t  = threadIdx.x;
    const int l0 = blockIdx.x * TL;
    const int h  = blockIdx.y;
    const int b  = blockIdx.z;

    // load Q tile (TL x 128)
    const float* qbase = Q + ((size_t)(b * L_ + l0) * INNER_) + h * E_;
    for (int i = t; i < TL * 32; i += 256) {
        int r = i >> 5, c4 = i & 31;
        *(float4*)&q_s[r][c4 * 4] =
            *(const float4*)(qbase + (size_t)r * INNER_ + c4 * 4);
    }
    if (t < TL) { m_s[t] = -1e30f; l_s[t] = 0.f; }

    const int r  = t >> 4;          // 0..15 (query row)
    const int c0 = (t & 15) * 4;    // score cols
    const int e0 = (t & 15) * 8;    // acc cols
    float acc[8] = {};

    const float scale = 0.08838834764831845f;   // 1/sqrt(128)

    for (int s0 = 0; s0 < S_; s0 += TS) {
        const int schunk = min(TS, S_ - s0);
        __syncthreads();   // prior AV reads of kv_s done; m_s/l_s visible

        // load K chunk (TS x 128), swizzled, zero-pad ragged rows
        const float* kbase = K + (size_t)s0 * INNER_ + h * E_;
        for (int i = t; i < TS * 32; i += 256) {
            int sr = i >> 5, c4 = i & 31;
            float4 v4 = (sr < schunk)
                ? *(const float4*)(kbase + (size_t)sr * INNER_ + c4 * 4)
                : make_float4(0.f, 0.f, 0.f, 0.f);
            *kvp(kv_s, sr, c4) = v4;
        }
        __syncthreads();

        // scores: each thread 1 row x 4 cols, dot over E=128
        float sc[4] = {};
        #pragma unroll 8
        for (int e = 0; e < 128; e += 4) {
            float4 qv = *(float4*)&q_s[r][e];
            #pragma unroll
            for (int j = 0; j < 4; j++) {
                float4 kvv = *kvp(kv_s, c0 + j, e >> 2);
                sc[j] += qv.x * kvv.x + qv.y * kvv.y + qv.z * kvv.z + qv.w * kvv.w;
            }
        }
        #pragma unroll
        for (int j = 0; j < 4; j++)
            sc_s[r][c0 + j] = (c0 + j < schunk) ? sc[j] * scale : -1e30f;
        __syncthreads();

        // online softmax update: one thread per row
        if (t < TL) {
            float m_old = m_s[t], mx = m_old;
            #pragma unroll 8
            for (int j = 0; j < TS; j++) mx = fmaxf(mx, sc_s[t][j]);
            float alpha = __expf(m_old - mx);
            float sum = 0.f;
            #pragma unroll 8
            for (int j = 0; j < TS; j++) {
                float p = __expf(sc_s[t][j] - mx);
                sc_s[t][j] = p;
                sum += p;
            }
            m_s[t] = mx;
            l_s[t] = l_s[t] * alpha + sum;
            alpha_s[t] = alpha;
        }
        __syncthreads();

        // rescale accumulators
        float alpha = alpha_s[r];
        #pragma unroll
        for (int i = 0; i < 8; i++) acc[i] *= alpha;

        // load V chunk (reuses kv_s; score-phase reads were fenced above)
        const float* vbase = V + (size_t)s0 * INNER_ + h * E_;
        for (int i = t; i < TS * 32; i += 256) {
            int sr = i >> 5, c4 = i & 31;
            float4 v4 = (sr < schunk)
                ? *(const float4*)(vbase + (size_t)sr * INNER_ + c4 * 4)
                : make_float4(0.f, 0.f, 0.f, 0.f);
            *kvp(kv_s, sr, c4) = v4;
        }
        __syncthreads();

        // acc += P @ V : each thread 1 row x 8 cols
        const int c4a = e0 >> 2;
        for (int s = 0; s < schunk; s++) {
            float p = sc_s[r][s];
            float4 va = *kvp(kv_s, s, c4a);
            float4 vb = *kvp(kv_s, s, c4a + 1);
            acc[0] += p * va.x; acc[1] += p * va.y;
            acc[2] += p * va.z; acc[3] += p * va.w;
            acc[4] += p * vb.x; acc[5] += p * vb.y;
            acc[6] += p * vb.z; acc[7] += p * vb.w;
        }
    }
    __syncthreads();

    const float inv_l = 1.f / l_s[r];
    float* obase = O + ((size_t)(b * L_ + l0 + r) * INNER_) + h * E_ + e0;
    #pragma unroll
    for (int i = 0; i < 8; i++) obase[i] = acc[i] * inv_l;
}

// ---------------------------------------------------------------------------
extern "C" void kernel_launch(void* const* d_in, const int* in_sizes, int n_in,
                              void* d_out, int out_size) {
    const float* tgt = (const float*)d_in[0];
    const float* src = (const float*)d_in[1];
    const float* val = (const float*)d_in[2];
    const float* Wq  = (const float*)d_in[3];
    const float* bq  = (const float*)d_in[4];
    const float* Wk  = (const float*)d_in[5];
    const float* bk  = (const float*)d_in[6];
    const float* Wv  = (const float*)d_in[7];
    const float* bv  = (const float*)d_in[8];
    const float* Wo  = (const float*)d_in[9];
    const float* bo  = (const float*)d_in[10];
    float* out = (float*)d_out;

    float *Q, *K, *V, *A;
    cudaGetSymbolAddress((void**)&Q, g_Q);
    cudaGetSymbolAddress((void**)&K, g_K);
    cudaGetSymbolAddress((void**)&V, g_V);
    cudaGetSymbolAddress((void**)&A, g_A);

    dim3 blk(256);

    // Q = tgt @ Wq + bq          (8192 x 1024 x 1024)
    gemm_bias_kernel<<<dim3(INNER_ / 64, (B_ * L_) / 64), blk>>>(
        tgt, Wq, bq, Q, B_ * L_, INNER_, DM);
    // K = src @ Wk + bk          (1000 x 1024 x 4096)
    gemm_bias_kernel<<<dim3(INNER_ / 64, (S_ + 63) / 64), blk>>>(
        src, Wk, bk, K, S_, INNER_, DL);
    // V = val @ Wv + bv
    gemm_bias_kernel<<<dim3(INNER_ / 64, (S_ + 63) / 64), blk>>>(
        val, Wv, bv, V, S_, INNER_, DL);
    // fused attention
    attn_kernel<<<dim3(L_ / TL, H_, B_), blk>>>(Q, K, V, A);
    // out = A @ Wo + bo          (8192 x 4096 x 1024)
    gemm_bias_kernel<<<dim3(DL / 64, (B_ * L_) / 64), blk>>>(
        A, Wo, bo, out, B_ * L_, DL, INNER_);
}

// round 3
// speedup vs baseline: 1.3707x; 1.3707x over previous
#include <cuda_runtime.h>
#include <math.h>

// Problem constants
#define B_   8
#define L_   1024
#define S_   1000
#define H_   8
#define E_   128
#define DM   1024
#define DL   4096
#define INNER_ 1024

// Scratch (allocation-free: __device__ globals)
__device__ float g_Q[B_ * L_ * INNER_];   // (B*L, H*E)
__device__ float g_K[S_ * INNER_];        // (S, H*E)
__device__ float g_V[S_ * INNER_];        // (S, H*E)
__device__ float g_A[B_ * L_ * INNER_];   // attention out (B*L, H*E)

// ---------------------------------------------------------------------------
// TF32 tensor-core GEMM: C[M,N] = A[M,K] @ B[K,N] + bias[N]
// BM=BN=128, BK=32, 256 threads = 8 warps in 2(M) x 4(N) grid,
// warp tile 64x32 via mma.sync.m16n8k8.tf32 (4 mfrag x 4 nfrag x 4 ksteps).
// Requires: N % 128 == 0, K % 32 == 0 (true for all 4 uses). M ragged OK.
// ---------------------------------------------------------------------------
#define BM 128
#define BN 128
#define BK 32
#define ASTRIDE 36    // BK + 4  -> fragment LDS banks (4g + c) bijective
#define BSTRIDE 136   // BN + 8  -> fragment LDS banks (8c + g) bijective

__device__ __forceinline__ unsigned f2tf(float f) {
    unsigned u;
    asm("cvt.rna.tf32.f32 %0, %1;" : "=r"(u) : "f"(f));
    return u;
}

__device__ __forceinline__ void mma_tf32(float* c, const unsigned* a, const unsigned* b) {
    asm("mma.sync.aligned.m16n8k8.row.col.f32.tf32.tf32.f32 "
        "{%0,%1,%2,%3}, {%4,%5,%6,%7}, {%8,%9}, {%0,%1,%2,%3};"
        : "+f"(c[0]), "+f"(c[1]), "+f"(c[2]), "+f"(c[3])
        : "r"(a[0]), "r"(a[1]), "r"(a[2]), "r"(a[3]), "r"(b[0]), "r"(b[1]));
}

__global__ __launch_bounds__(256)
void gemm_tf32_kernel(const float* __restrict__ A,
                      const float* __restrict__ B,
                      const float* __restrict__ bias,
                      float* __restrict__ C,
                      int M, int N, int K) {
    __shared__ unsigned As[BM][ASTRIDE];   // row-major M x K tile (tf32 bits)
    __shared__ unsigned Bs[BK][BSTRIDE];   // row-major K x N tile (tf32 bits)

    const int t    = threadIdx.x;
    const int lane = t & 31;
    const int wid  = t >> 5;
    const int bm   = blockIdx.y * BM;
    const int bn   = blockIdx.x * BN;

    const int wm = (wid >> 2) * 64;   // warp M offset: 0 / 64
    const int wn = (wid & 3) * 32;    // warp N offset: 0/32/64/96
    const int g  = lane >> 2;         // 0..7
    const int cc = lane & 3;          // 0..3

    // loader indices (4 float4 each for A and B per iter)
    const int am[4]  = { (t + 0) >> 3,  (t + 256) >> 3,  (t + 512) >> 3,  (t + 768) >> 3 };
    const int ak4    = (t & 7) * 4;
    const int bkr[4] = { (t + 0) >> 5,  (t + 256) >> 5,  (t + 512) >> 5,  (t + 768) >> 5 };
    const int bn4    = (t & 31) * 4;

    float acc[4][4][4] = {};
    float4 pa[4], pb[4];
    const float4 z4 = make_float4(0.f, 0.f, 0.f, 0.f);

    const int niter = K / BK;

    // prefetch tile 0 into registers
    #pragma unroll
    for (int i = 0; i < 4; i++) {
        pa[i] = (bm + am[i] < M)
              ? *(const float4*)(A + (size_t)(bm + am[i]) * K + ak4) : z4;
        pb[i] = *(const float4*)(B + (size_t)bkr[i] * N + bn + bn4);
    }

    for (int it = 0; it < niter; ++it) {
        // store staged tile to smem (tf32-rounded)
        #pragma unroll
        for (int i = 0; i < 4; i++) {
            uint4 ua = make_uint4(f2tf(pa[i].x), f2tf(pa[i].y), f2tf(pa[i].z), f2tf(pa[i].w));
            *(uint4*)&As[am[i]][ak4] = ua;
            uint4 ub = make_uint4(f2tf(pb[i].x), f2tf(pb[i].y), f2tf(pb[i].z), f2tf(pb[i].w));
            *(uint4*)&Bs[bkr[i]][bn4] = ub;
        }
        __syncthreads();

        // prefetch next tile (overlaps with compute below)
        if (it + 1 < niter) {
            const int k0 = (it + 1) * BK;
            #pragma unroll
            for (int i = 0; i < 4; i++) {
                pa[i] = (bm + am[i] < M)
                      ? *(const float4*)(A + (size_t)(bm + am[i]) * K + k0 + ak4) : z4;
                pb[i] = *(const float4*)(B + (size_t)(k0 + bkr[i]) * N + bn + bn4);
            }
        }

        // compute: 4 k-steps of 8
        #pragma unroll
        for (int ks = 0; ks < 4; ks++) {
            const int kk = ks * 8;
            unsigned af[4][4], bf[4][2];
            #pragma unroll
            for (int mf = 0; mf < 4; mf++) {
                const int rb = wm + mf * 16;
                af[mf][0] = As[rb + g    ][kk + cc    ];
                af[mf][1] = As[rb + g + 8][kk + cc    ];
                af[mf][2] = As[rb + g    ][kk + cc + 4];
                af[mf][3] = As[rb + g + 8][kk + cc + 4];
            }
            #pragma unroll
            for (int nf = 0; nf < 4; nf++) {
                const int cb = wn + nf * 8;
                bf[nf][0] = Bs[kk + cc    ][cb + g];
                bf[nf][1] = Bs[kk + cc + 4][cb + g];
            }
            #pragma unroll
            for (int mf = 0; mf < 4; mf++)
                #pragma unroll
                for (int nf = 0; nf < 4; nf++)
                    mma_tf32(acc[mf][nf], af[mf], bf[nf]);
        }
        __syncthreads();
    }

    // epilogue: add bias, store (cols 2c,2c+1 adjacent -> float2 stores)
    #pragma unroll
    for (int mf = 0; mf < 4; mf++) {
        const int row0 = bm + wm + mf * 16 + g;
        #pragma unroll
        for (int nf = 0; nf < 4; nf++) {
            const int col = bn + wn + nf * 8 + 2 * cc;
            const float2 bb = *(const float2*)(bias + col);
            if (row0 < M) {
                float2 o = make_float2(acc[mf][nf][0] + bb.x, acc[mf][nf][1] + bb.y);
                *(float2*)(C + (size_t)row0 * N + col) = o;
            }
            if (row0 + 8 < M) {
                float2 o = make_float2(acc[mf][nf][2] + bb.x, acc[mf][nf][3] + bb.y);
                *(float2*)(C + (size_t)(row0 + 8) * N + col) = o;
            }
        }
    }
}

// ---------------------------------------------------------------------------
// Fused attention: per (b, h, 16-row L tile), flash-style online softmax
// over S=1000 in chunks of 64. fp32 throughout. (unchanged from R2)
// ---------------------------------------------------------------------------
#define TL 16
#define TS 64

__device__ __forceinline__ float4* kvp(float (*kv)[128], int srow, int c4) {
    return (float4*)&kv[srow][((c4 ^ (srow >> 2)) & 31) << 2];
}

__global__ __launch_bounds__(256)
void attn_kernel(const float* __restrict__ Q,
                 const float* __restrict__ K,
                 const float* __restrict__ V,
                 float* __restrict__ O) {
    __shared__ float q_s[TL][128];
    __shared__ float kv_s[TS][128];
    __shared__ float sc_s[TL][TS];
    __shared__ float m_s[TL], l_s[TL], alpha_s[TL];

    const int t  = threadIdx.x;
    const int l0 = blockIdx.x * TL;
    const int h  = blockIdx.y;
    const int b  = blockIdx.z;

    const float* qbase = Q + ((size_t)(b * L_ + l0) * INNER_) + h * E_;
    for (int i = t; i < TL * 32; i += 256) {
        int r = i >> 5, c4 = i & 31;
        *(float4*)&q_s[r][c4 * 4] =
            *(const float4*)(qbase + (size_t)r * INNER_ + c4 * 4);
    }
    if (t < TL) { m_s[t] = -1e30f; l_s[t] = 0.f; }

    const int r  = t >> 4;
    const int c0 = (t & 15) * 4;
    const int e0 = (t & 15) * 8;
    float acc[8] = {};

    const float scale = 0.08838834764831845f;   // 1/sqrt(128)

    for (int s0 = 0; s0 < S_; s0 += TS) {
        const int schunk = min(TS, S_ - s0);
        __syncthreads();

        const float* kbase = K + (size_t)s0 * INNER_ + h * E_;
        for (int i = t; i < TS * 32; i += 256) {
            int sr = i >> 5, c4 = i & 31;
            float4 v4 = (sr < schunk)
                ? *(const float4*)(kbase + (size_t)sr * INNER_ + c4 * 4)
                : make_float4(0.f, 0.f, 0.f, 0.f);
            *kvp(kv_s, sr, c4) = v4;
        }
        __syncthreads();

        float sc[4] = {};
        #pragma unroll 8
        for (int e = 0; e < 128; e += 4) {
            float4 qv = *(float4*)&q_s[r][e];
            #pragma unroll
            for (int j = 0; j < 4; j++) {
                float4 kvv = *kvp(kv_s, c0 + j, e >> 2);
                sc[j] += qv.x * kvv.x + qv.y * kvv.y + qv.z * kvv.z + qv.w * kvv.w;
            }
        }
        #pragma unroll
        for (int j = 0; j < 4; j++)
            sc_s[r][c0 + j] = (c0 + j < schunk) ? sc[j] * scale : -1e30f;
        __syncthreads();

        if (t < TL) {
            float m_old = m_s[t], mx = m_old;
            #pragma unroll 8
            for (int j = 0; j < TS; j++) mx = fmaxf(mx, sc_s[t][j]);
            float alpha = __expf(m_old - mx);
            float sum = 0.f;
            #pragma unroll 8
            for (int j = 0; j < TS; j++) {
                float p = __expf(sc_s[t][j] - mx);
                sc_s[t][j] = p;
                sum += p;
            }
            m_s[t] = mx;
            l_s[t] = l_s[t] * alpha + sum;
            alpha_s[t] = alpha;
        }
        __syncthreads();

        float alpha = alpha_s[r];
        #pragma unroll
        for (int i = 0; i < 8; i++) acc[i] *= alpha;

        const float* vbase = V + (size_t)s0 * INNER_ + h * E_;
        for (int i = t; i < TS * 32; i += 256) {
            int sr = i >> 5, c4 = i & 31;
            float4 v4 = (sr < schunk)
                ? *(const float4*)(vbase + (size_t)sr * INNER_ + c4 * 4)
                : make_float4(0.f, 0.f, 0.f, 0.f);
            *kvp(kv_s, sr, c4) = v4;
        }
        __syncthreads();

        const int c4a = e0 >> 2;
        for (int s = 0; s < schunk; s++) {
            float p = sc_s[r][s];
            float4 va = *kvp(kv_s, s, c4a);
            float4 vb = *kvp(kv_s, s, c4a + 1);
            acc[0] += p * va.x; acc[1] += p * va.y;
            acc[2] += p * va.z; acc[3] += p * va.w;
            acc[4] += p * vb.x; acc[5] += p * vb.y;
            acc[6] += p * vb.z; acc[7] += p * vb.w;
        }
    }
    __syncthreads();

    const float inv_l = 1.f / l_s[r];
    float* obase = O + ((size_t)(b * L_ + l0 + r) * INNER_) + h * E_ + e0;
    #pragma unroll
    for (int i = 0; i < 8; i++) obase[i] = acc[i] * inv_l;
}

// ---------------------------------------------------------------------------
extern "C" void kernel_launch(void* const* d_in, const int* in_sizes, int n_in,
                              void* d_out, int out_size) {
    const float* tgt = (const float*)d_in[0];
    const float* src = (const float*)d_in[1];
    const float* val = (const float*)d_in[2];
    const float* Wq  = (const float*)d_in[3];
    const float* bq  = (const float*)d_in[4];
    const float* Wk  = (const float*)d_in[5];
    const float* bk  = (const float*)d_in[6];
    const float* Wv  = (const float*)d_in[7];
    const float* bv  = (const float*)d_in[8];
    const float* Wo  = (const float*)d_in[9];
    const float* bo  = (const float*)d_in[10];
    float* out = (float*)d_out;

    float *Q, *K, *V, *A;
    cudaGetSymbolAddress((void**)&Q, g_Q);
    cudaGetSymbolAddress((void**)&K, g_K);
    cudaGetSymbolAddress((void**)&V, g_V);
    cudaGetSymbolAddress((void**)&A, g_A);

    dim3 blk(256);

    // Q = tgt @ Wq + bq          (8192 x 1024 x 1024)
    gemm_tf32_kernel<<<dim3(INNER_ / BN, (B_ * L_) / BM), blk>>>(
        tgt, Wq, bq, Q, B_ * L_, INNER_, DM);
    // K = src @ Wk + bk          (1000 x 1024 x 4096)
    gemm_tf32_kernel<<<dim3(INNER_ / BN, (S_ + BM - 1) / BM), blk>>>(
        src, Wk, bk, K, S_, INNER_, DL);
    // V = val @ Wv + bv
    gemm_tf32_kernel<<<dim3(INNER_ / BN, (S_ + BM - 1) / BM), blk>>>(
        val, Wv, bv, V, S_, INNER_, DL);
    // fused attention
    attn_kernel<<<dim3(L_ / TL, H_, B_), blk>>>(Q, K, V, A);
    // out = A @ Wo + bo          (8192 x 4096 x 1024)
    gemm_tf32_kernel<<<dim3(DL / BN, (B_ * L_) / BM), blk>>>(
        A, Wo, bo, out, B_ * L_, DL, INNER_);
}

// round 5
// speedup vs baseline: 1.3709x; 1.0001x over previous
#include <cuda_runtime.h>
#include <math.h>

// Problem constants
#define B_   8
#define L_   1024
#define S_   1000
#define H_   8
#define E_   128
#define DM   1024
#define DL   4096
#define INNER_ 1024

// Scratch (allocation-free: __device__ globals)
__device__ float g_Q[B_ * L_ * INNER_];   // (B*L, H*E)
__device__ float g_K[S_ * INNER_];        // (S, H*E)
__device__ float g_V[S_ * INNER_];        // (S, H*E)
__device__ float g_A[B_ * L_ * INNER_];   // attention out (B*L, H*E)

// ---------------------------------------------------------------------------
// TF32 tensor-core GEMM: C[M,N] = A[M,K] @ B[K,N] + bias[N]
// BM=BN=128, BK=32, 256 threads = 8 warps in 2(M) x 4(N) grid,
// warp tile 64x32 via mma.sync.m16n8k8.tf32 (4 mfrag x 4 nfrag x 4 ksteps).
// Requires: N % 128 == 0, K % 32 == 0 (true for all 4 uses). M ragged OK.
// ---------------------------------------------------------------------------
#define BM 128
#define BN 128
#define BK 32
#define ASTRIDE 36    // BK + 4  -> fragment LDS banks (4g + c) bijective
#define BSTRIDE 136   // BN + 8  -> fragment LDS banks (8c + g) bijective

__device__ __forceinline__ unsigned f2tf(float f) {
    unsigned u;
    asm("cvt.rna.tf32.f32 %0, %1;" : "=r"(u) : "f"(f));
    return u;
}

__device__ __forceinline__ void mma_tf32(float* c, const unsigned* a, const unsigned* b) {
    asm("mma.sync.aligned.m16n8k8.row.col.f32.tf32.tf32.f32 "
        "{%0,%1,%2,%3}, {%4,%5,%6,%7}, {%8,%9}, {%0,%1,%2,%3};"
        : "+f"(c[0]), "+f"(c[1]), "+f"(c[2]), "+f"(c[3])
        : "r"(a[0]), "r"(a[1]), "r"(a[2]), "r"(a[3]), "r"(b[0]), "r"(b[1]));
}

__global__ __launch_bounds__(256)
void gemm_tf32_kernel(const float* __restrict__ A,
                      const float* __restrict__ B,
                      const float* __restrict__ bias,
                      float* __restrict__ C,
                      int M, int N, int K) {
    __shared__ unsigned As[BM][ASTRIDE];   // row-major M x K tile (tf32 bits)
    __shared__ unsigned Bs[BK][BSTRIDE];   // row-major K x N tile (tf32 bits)

    const int t    = threadIdx.x;
    const int lane = t & 31;
    const int wid  = t >> 5;
    const int bm   = blockIdx.y * BM;
    const int bn   = blockIdx.x * BN;

    const int wm = (wid >> 2) * 64;   // warp M offset: 0 / 64
    const int wn = (wid & 3) * 32;    // warp N offset: 0/32/64/96
    const int g  = lane >> 2;         // 0..7
    const int cc = lane & 3;          // 0..3

    // loader indices (4 float4 each for A and B per iter)
    const int am[4]  = { (t + 0) >> 3,  (t + 256) >> 3,  (t + 512) >> 3,  (t + 768) >> 3 };
    const int ak4    = (t & 7) * 4;
    const int bkr[4] = { (t + 0) >> 5,  (t + 256) >> 5,  (t + 512) >> 5,  (t + 768) >> 5 };
    const int bn4    = (t & 31) * 4;

    float acc[4][4][4] = {};
    float4 pa[4], pb[4];
    const float4 z4 = make_float4(0.f, 0.f, 0.f, 0.f);

    const int niter = K / BK;

    // prefetch tile 0 into registers
    #pragma unroll
    for (int i = 0; i < 4; i++) {
        pa[i] = (bm + am[i] < M)
              ? *(const float4*)(A + (size_t)(bm + am[i]) * K + ak4) : z4;
        pb[i] = *(const float4*)(B + (size_t)bkr[i] * N + bn + bn4);
    }

    for (int it = 0; it < niter; ++it) {
        // store staged tile to smem (tf32-rounded)
        #pragma unroll
        for (int i = 0; i < 4; i++) {
            uint4 ua = make_uint4(f2tf(pa[i].x), f2tf(pa[i].y), f2tf(pa[i].z), f2tf(pa[i].w));
            *(uint4*)&As[am[i]][ak4] = ua;
            uint4 ub = make_uint4(f2tf(pb[i].x), f2tf(pb[i].y), f2tf(pb[i].z), f2tf(pb[i].w));
            *(uint4*)&Bs[bkr[i]][bn4] = ub;
        }
        __syncthreads();

        // prefetch next tile (overlaps with compute below)
        if (it + 1 < niter) {
            const int k0 = (it + 1) * BK;
            #pragma unroll
            for (int i = 0; i < 4; i++) {
                pa[i] = (bm + am[i] < M)
                      ? *(const float4*)(A + (size_t)(bm + am[i]) * K + k0 + ak4) : z4;
                pb[i] = *(const float4*)(B + (size_t)(k0 + bkr[i]) * N + bn + bn4);
            }
        }

        // compute: 4 k-steps of 8
        #pragma unroll
        for (int ks = 0; ks < 4; ks++) {
            const int kk = ks * 8;
            unsigned af[4][4], bf[4][2];
            #pragma unroll
            for (int mf = 0; mf < 4; mf++) {
                const int rb = wm + mf * 16;
                af[mf][0] = As[rb + g    ][kk + cc    ];
                af[mf][1] = As[rb + g + 8][kk + cc    ];
                af[mf][2] = As[rb + g    ][kk + cc + 4];
                af[mf][3] = As[rb + g + 8][kk + cc + 4];
            }
            #pragma unroll
            for (int nf = 0; nf < 4; nf++) {
                const int cb = wn + nf * 8;
                bf[nf][0] = Bs[kk + cc    ][cb + g];
                bf[nf][1] = Bs[kk + cc + 4][cb + g];
            }
            #pragma unroll
            for (int mf = 0; mf < 4; mf++)
                #pragma unroll
                for (int nf = 0; nf < 4; nf++)
                    mma_tf32(acc[mf][nf], af[mf], bf[nf]);
        }
        __syncthreads();
    }

    // epilogue: add bias, store (cols 2c,2c+1 adjacent -> float2 stores)
    #pragma unroll
    for (int mf = 0; mf < 4; mf++) {
        const int row0 = bm + wm + mf * 16 + g;
        #pragma unroll
        for (int nf = 0; nf < 4; nf++) {
            const int col = bn + wn + nf * 8 + 2 * cc;
            const float2 bb = *(const float2*)(bias + col);
            if (row0 < M) {
                float2 o = make_float2(acc[mf][nf][0] + bb.x, acc[mf][nf][1] + bb.y);
                *(float2*)(C + (size_t)row0 * N + col) = o;
            }
            if (row0 + 8 < M) {
                float2 o = make_float2(acc[mf][nf][2] + bb.x, acc[mf][nf][3] + bb.y);
                *(float2*)(C + (size_t)(row0 + 8) * N + col) = o;
            }
        }
    }
}

// ---------------------------------------------------------------------------
// Fused attention: per (b, h, 16-row L tile), flash-style online softmax
// over S=1000 in chunks of 64. fp32 throughout. (unchanged from R2)
// ---------------------------------------------------------------------------
#define TL 16
#define TS 64

__device__ __forceinline__ float4* kvp(float (*kv)[128], int srow, int c4) {
    return (float4*)&kv[srow][((c4 ^ (srow >> 2)) & 31) << 2];
}

__global__ __launch_bounds__(256)
void attn_kernel(const float* __restrict__ Q,
                 const float* __restrict__ K,
                 const float* __restrict__ V,
                 float* __restrict__ O) {
    __shared__ float q_s[TL][128];
    __shared__ float kv_s[TS][128];
    __shared__ float sc_s[TL][TS];
    __shared__ float m_s[TL], l_s[TL], alpha_s[TL];

    const int t  = threadIdx.x;
    const int l0 = blockIdx.x * TL;
    const int h  = blockIdx.y;
    const int b  = blockIdx.z;

    const float* qbase = Q + ((size_t)(b * L_ + l0) * INNER_) + h * E_;
    for (int i = t; i < TL * 32; i += 256) {
        int r = i >> 5, c4 = i & 31;
        *(float4*)&q_s[r][c4 * 4] =
            *(const float4*)(qbase + (size_t)r * INNER_ + c4 * 4);
    }
    if (t < TL) { m_s[t] = -1e30f; l_s[t] = 0.f; }

    const int r  = t >> 4;
    const int c0 = (t & 15) * 4;
    const int e0 = (t & 15) * 8;
    float acc[8] = {};

    const float scale = 0.08838834764831845f;   // 1/sqrt(128)

    for (int s0 = 0; s0 < S_; s0 += TS) {
        const int schunk = min(TS, S_ - s0);
        __syncthreads();

        const float* kbase = K + (size_t)s0 * INNER_ + h * E_;
        for (int i = t; i < TS * 32; i += 256) {
            int sr = i >> 5, c4 = i & 31;
            float4 v4 = (sr < schunk)
                ? *(const float4*)(kbase + (size_t)sr * INNER_ + c4 * 4)
                : make_float4(0.f, 0.f, 0.f, 0.f);
            *kvp(kv_s, sr, c4) = v4;
        }
        __syncthreads();

        float sc[4] = {};
        #pragma unroll 8
        for (int e = 0; e < 128; e += 4) {
            float4 qv = *(float4*)&q_s[r][e];
            #pragma unroll
            for (int j = 0; j < 4; j++) {
                float4 kvv = *kvp(kv_s, c0 + j, e >> 2);
                sc[j] += qv.x * kvv.x + qv.y * kvv.y + qv.z * kvv.z + qv.w * kvv.w;
            }
        }
        #pragma unroll
        for (int j = 0; j < 4; j++)
            sc_s[r][c0 + j] = (c0 + j < schunk) ? sc[j] * scale : -1e30f;
        __syncthreads();

        if (t < TL) {
            float m_old = m_s[t], mx = m_old;
            #pragma unroll 8
            for (int j = 0; j < TS; j++) mx = fmaxf(mx, sc_s[t][j]);
            float alpha = __expf(m_old - mx);
            float sum = 0.f;
            #pragma unroll 8
            for (int j = 0; j < TS; j++) {
                float p = __expf(sc_s[t][j] - mx);
                sc_s[t][j] = p;
                sum += p;
            }
            m_s[t] = mx;
            l_s[t] = l_s[t] * alpha + sum;
            alpha_s[t] = alpha;
        }
        __syncthreads();

        float alpha = alpha_s[r];
        #pragma unroll
        for (int i = 0; i < 8; i++) acc[i] *= alpha;

        const float* vbase = V + (size_t)s0 * INNER_ + h * E_;
        for (int i = t; i < TS * 32; i += 256) {
            int sr = i >> 5, c4 = i & 31;
            float4 v4 = (sr < schunk)
                ? *(const float4*)(vbase + (size_t)sr * INNER_ + c4 * 4)
                : make_float4(0.f, 0.f, 0.f, 0.f);
            *kvp(kv_s, sr, c4) = v4;
        }
        __syncthreads();

        const int c4a = e0 >> 2;
        for (int s = 0; s < schunk; s++) {
            float p = sc_s[r][s];
            float4 va = *kvp(kv_s, s, c4a);
            float4 vb = *kvp(kv_s, s, c4a + 1);
            acc[0] += p * va.x; acc[1] += p * va.y;
            acc[2] += p * va.z; acc[3] += p * va.w;
            acc[4] += p * vb.x; acc[5] += p * vb.y;
            acc[6] += p * vb.z; acc[7] += p * vb.w;
        }
    }
    __syncthreads();

    const float inv_l = 1.f / l_s[r];
    float* obase = O + ((size_t)(b * L_ + l0 + r) * INNER_) + h * E_ + e0;
    #pragma unroll
    for (int i = 0; i < 8; i++) obase[i] = acc[i] * inv_l;
}

// ---------------------------------------------------------------------------
extern "C" void kernel_launch(void* const* d_in, const int* in_sizes, int n_in,
                              void* d_out, int out_size) {
    const float* tgt = (const float*)d_in[0];
    const float* src = (const float*)d_in[1];
    const float* val = (const float*)d_in[2];
    const float* Wq  = (const float*)d_in[3];
    const float* bq  = (const float*)d_in[4];
    const float* Wk  = (const float*)d_in[5];
    const float* bk  = (const float*)d_in[6];
    const float* Wv  = (const float*)d_in[7];
    const float* bv  = (const float*)d_in[8];
    const float* Wo  = (const float*)d_in[9];
    const float* bo  = (const float*)d_in[10];
    float* out = (float*)d_out;

    float *Q, *K, *V, *A;
    cudaGetSymbolAddress((void**)&Q, g_Q);
    cudaGetSymbolAddress((void**)&K, g_K);
    cudaGetSymbolAddress((void**)&V, g_V);
    cudaGetSymbolAddress((void**)&A, g_A);

    dim3 blk(256);

    // Q = tgt @ Wq + bq          (8192 x 1024 x 1024)
    gemm_tf32_kernel<<<dim3(INNER_ / BN, (B_ * L_) / BM), blk>>>(
        tgt, Wq, bq, Q, B_ * L_, INNER_, DM);
    // K = src @ Wk + bk          (1000 x 1024 x 4096)
    gemm_tf32_kernel<<<dim3(INNER_ / BN, (S_ + BM - 1) / BM), blk>>>(
        src, Wk, bk, K, S_, INNER_, DL);
    // V = val @ Wv + bv
    gemm_tf32_kernel<<<dim3(INNER_ / BN, (S_ + BM - 1) / BM), blk>>>(
        val, Wv, bv, V, S_, INNER_, DL);
    // fused attention
    attn_kernel<<<dim3(L_ / TL, H_, B_), blk>>>(Q, K, V, A);
    // out = A @ Wo + bo          (8192 x 4096 x 1024)
    gemm_tf32_kernel<<<dim3(DL / BN, (B_ * L_) / BM), blk>>>(
        A, Wo, bo, out, B_ * L_, DL, INNER_);
}